// round 1
// baseline (speedup 1.0000x reference)
#include <cuda_runtime.h>
#include <cuda_bf16.h>

// Problem constants
#define NN 375
#define CC 5
#define FF 64
#define DD 13
#define WARPS_PER_BLOCK 4
#define THREADS (WARPS_PER_BLOCK * 32)

// start(s) of segment s: {0,12,25,38,51} == (s==0 ? 0 : 13*s-1)
__device__ __forceinline__ int seg_start(int s) {
    return s == 0 ? 0 : 13 * s - 1;
}

__global__ void __launch_bounds__(THREADS, 1)
token_assign_kernel(const float* __restrict__ pic,
                    const float* __restrict__ t0,
                    const float* __restrict__ t1,
                    const float* __restrict__ t2,
                    const float* __restrict__ t3,
                    const float* __restrict__ t4,
                    float* __restrict__ out) {
    __shared__ float T[CC][DD];                       // 5 x 13 tokens
    __shared__ float sp[WARPS_PER_BLOCK][CC * FF];    // per-warp picture row (320 floats)
    __shared__ float sD[WARPS_PER_BLOCK][25];         // per-warp 5x5 cost matrix
    __shared__ int   sAssign[WARPS_PER_BLOCK][CC];    // per-warp assignment

    const int tid = threadIdx.x;

    // Stage tokens into shared (once per block)
    if (tid < CC * DD) {
        int s = tid / DD, j = tid % DD;
        const float* tp;
        switch (s) {
            case 0: tp = t0; break;
            case 1: tp = t1; break;
            case 2: tp = t2; break;
            case 3: tp = t3; break;
            default: tp = t4; break;
        }
        T[s][j] = tp[j];
    }
    __syncthreads();

    const int warp = tid >> 5;
    const int lane = tid & 31;
    const int n = blockIdx.x * WARPS_PER_BLOCK + warp;
    if (n >= NN) return;

    const float* p = pic + (size_t)n * (CC * FF);
    float*       o = out + (size_t)n * (CC * FF);

    // Coalesced stage of the 320-float sample into shared
    #pragma unroll
    for (int k = 0; k < (CC * FF) / 32; k++) {
        sp[warp][lane + 32 * k] = p[lane + 32 * k];
    }
    __syncwarp();

    // 25 lanes: one (channel c, segment s) pair each.
    // Dmat = full_sq - seg_sq + diff_sq  (mirrors reference formula & fp32 order)
    if (lane < 25) {
        const int c = lane / 5;
        const int s = lane % 5;
        const float* row = &sp[warp][c * FF];
        const int st = seg_start(s);

        float seg_sq = 0.f, diff_sq = 0.f;
        #pragma unroll
        for (int j = 0; j < DD; j++) {
            float v = row[st + j];
            float d = v - T[s][j];
            seg_sq  += v * v;
            diff_sq += d * d;
        }
        float full_sq = 0.f;
        #pragma unroll
        for (int f = 0; f < FF; f++) {
            float v = row[f];
            full_sq += v * v;
        }
        sD[warp][lane] = full_sq - seg_sq + diff_sq;
    }
    __syncwarp();

    // Greedy matching, serial on lane 0 (125 compares).
    // Matches jnp.argmin: first minimum in row-major flat order (strict <).
    if (lane == 0) {
        bool rowU[5] = {false, false, false, false, false};
        bool colU[5] = {false, false, false, false, false};
        #pragma unroll
        for (int it = 0; it < 5; it++) {
            float best = 1e30f;
            int   bi   = 0;
            #pragma unroll
            for (int idx = 0; idx < 25; idx++) {
                int r  = idx / 5;
                int cc = idx % 5;
                float v = (rowU[r] || colU[cc]) ? 1e30f : sD[warp][idx];
                if (v < best) { best = v; bi = idx; }
            }
            int r  = bi / 5;
            int cc = bi % 5;
            sAssign[warp][r] = cc;
            rowU[r] = true;
            colU[cc] = true;
        }
    }
    __syncwarp();

    // Write output: out[n,c,f] = T[assign[c]][f - start(c)] if in range else 0
    #pragma unroll
    for (int k = 0; k < (CC * FF) / 32; k++) {
        int i = lane + 32 * k;
        int c = i >> 6;       // channel
        int f = i & 63;       // feature
        int rel = f - seg_start(c);
        float val = 0.f;
        if (rel >= 0 && rel < DD) {
            val = T[sAssign[warp][c]][rel];
        }
        o[i] = val;
    }
}

extern "C" void kernel_launch(void* const* d_in, const int* in_sizes, int n_in,
                              void* d_out, int out_size) {
    const float* pic = (const float*)d_in[0];
    const float* t0  = (const float*)d_in[1];
    const float* t1  = (const float*)d_in[2];
    const float* t2  = (const float*)d_in[3];
    const float* t3  = (const float*)d_in[4];
    const float* t4  = (const float*)d_in[5];
    float* out = (float*)d_out;

    const int blocks = (NN + WARPS_PER_BLOCK - 1) / WARPS_PER_BLOCK;  // 94
    token_assign_kernel<<<blocks, THREADS>>>(pic, t0, t1, t2, t3, t4, out);
}

// round 4
// speedup vs baseline: 1.3077x; 1.3077x over previous
#include <cuda_runtime.h>
#include <cuda_bf16.h>

#define NN 375
#define CC 5
#define FF 64
#define DD 13
#define INF30 1e30f

__device__ __forceinline__ int seg_start(int s) { return s == 0 ? 0 : 13 * s - 1; }

__device__ __forceinline__ float tok_load(int q,
                                          const float* __restrict__ t0,
                                          const float* __restrict__ t1,
                                          const float* __restrict__ t2,
                                          const float* __restrict__ t3,
                                          const float* __restrict__ t4) {
    int s = q / DD;
    int j = q - DD * s;
    const float* tp = (s == 0) ? t0 : (s == 1) ? t1 : (s == 2) ? t2 : (s == 3) ? t3 : t4;
    return tp[j];
}

__global__ void __launch_bounds__(32)
token_kernel(const float* __restrict__ pic,
             const float* __restrict__ t0, const float* __restrict__ t1,
             const float* __restrict__ t2, const float* __restrict__ t3,
             const float* __restrict__ t4,
             float* __restrict__ out) {
    __shared__ float sp[CC * FF];   // 320-float picture row
    __shared__ float Ts[CC * DD + 3];  // 65 token values (padded)

    const int lane = threadIdx.x;
    const int n = blockIdx.x;

    // ---- Issue ALL global loads up front (overlapped latency) ----
    const float4* p4 = (const float4*)(pic + (size_t)n * (CC * FF));
    float4 r0 = p4[lane];
    float4 r1 = p4[lane + 32];
    float4 r2 = make_float4(0.f, 0.f, 0.f, 0.f);
    if (lane < 16) r2 = p4[lane + 64];

    float tv0 = tok_load(lane, t0, t1, t2, t3, t4);        // q in [0,32)
    float tv1 = tok_load(lane + 32, t0, t1, t2, t3, t4);   // q in [32,64)
    float tv2 = (lane == 0) ? t4[12] : 0.f;                // q == 64

    // ---- Per-lane channel partial sums of squares (registers only) ----
    // float4 at position p covers elems [4p, 4p+4) -> entirely inside one 64-wide channel.
    float s0 = r0.x * r0.x + r0.y * r0.y + r0.z * r0.z + r0.w * r0.w;  // ch = lane>>4
    float s1 = r1.x * r1.x + r1.y * r1.y + r1.z * r1.z + r1.w * r1.w;  // ch = (lane>>4)+2
    float s2 = r2.x * r2.x + r2.y * r2.y + r2.z * r2.z + r2.w * r2.w;  // ch = 4 (lanes<16; else 0)

    float fs[5];
    bool lo = (lane < 16);
    fs[0] = lo ? s0 : 0.f;
    fs[1] = lo ? 0.f : s0;
    fs[2] = lo ? s1 : 0.f;
    fs[3] = lo ? 0.f : s1;
    fs[4] = s2;

    // Butterfly reduce all 5 channel sums; every lane ends with full_sq[0..4]
    #pragma unroll
    for (int off = 16; off >= 1; off >>= 1) {
        #pragma unroll
        for (int c = 0; c < 5; c++)
            fs[c] += __shfl_xor_sync(0xffffffffu, fs[c], off);
    }

    // ---- Stage row + tokens into shared ----
    float4* sp4 = (float4*)sp;
    sp4[lane]      = r0;
    sp4[lane + 32] = r1;
    if (lane < 16) sp4[lane + 64] = r2;
    Ts[lane]      = tv0;
    Ts[lane + 32] = tv1;
    if (lane == 0) Ts[64] = tv2;
    __syncwarp();

    // ---- Dmat entry per lane (lanes 0..24): D[c][s] = full_sq[c] - seg_sq + diff_sq ----
    float Dl = 0.f;
    if (lane < 25) {
        int c = lane / 5;
        int s = lane - 5 * c;
        const float* row = &sp[c * FF];
        const float* tok = &Ts[s * DD];
        int st = seg_start(s);

        float sa = 0.f, sb = 0.f;   // seg_sq, two accumulators
        float da = 0.f, db = 0.f;   // diff_sq, two accumulators
        #pragma unroll
        for (int j = 0; j < DD; j += 2) {
            float v = row[st + j];
            float d = v - tok[j];
            sa += v * v;
            da += d * d;
            if (j + 1 < DD) {
                float v2 = row[st + j + 1];
                float d2 = v2 - tok[j + 1];
                sb += v2 * v2;
                db += d2 * d2;
            }
        }
        float fsq = fs[0];
        #pragma unroll
        for (int c2 = 1; c2 < 5; c2++) fsq = (c == c2) ? fs[c2] : fsq;
        Dl = fsq - (sa + sb) + (da + db);
    }

    // ---- Gather the 5x5 matrix into every lane's registers ----
    float Dv[25];
    #pragma unroll
    for (int i = 0; i < 25; i++) Dv[i] = __shfl_sync(0xffffffffu, Dl, i);

    // ---- Greedy matching, redundantly on all lanes (tree argmin, jnp tie-break) ----
    unsigned excl = 0u;
    int asg[5] = {0, 0, 0, 0, 0};
    #pragma unroll
    for (int it = 0; it < 5; it++) {
        // masked values
        float a[32];
        #pragma unroll
        for (int i = 0; i < 25; i++) a[i] = ((excl >> i) & 1u) ? INF30 : Dv[i];
        #pragma unroll
        for (int i = 25; i < 32; i++) a[i] = INF30;
        // value min tree (depth 5, FMNMX)
        #pragma unroll
        for (int off = 16; off >= 1; off >>= 1)
            #pragma unroll
            for (int i = 0; i < off; i++) a[i] = fminf(a[i], a[i + off]);
        float mn = a[0];
        // first index matching mn (parallel tests + int min tree)
        int ci[32];
        #pragma unroll
        for (int i = 0; i < 25; i++)
            ci[i] = (((excl >> i) & 1u) == 0u && Dv[i] == mn) ? i : 99;
        #pragma unroll
        for (int i = 25; i < 32; i++) ci[i] = 99;
        #pragma unroll
        for (int off = 16; off >= 1; off >>= 1)
            #pragma unroll
            for (int i = 0; i < off; i++) ci[i] = min(ci[i], ci[i + off]);
        int idx = ci[0];
        int r = idx / 5;
        int c = idx - 5 * r;
        excl |= (0x1Fu << (5 * r)) | (0x108421u << c);
        #pragma unroll
        for (int r2 = 0; r2 < 5; r2++)
            if (r == r2) asg[r2] = c;
    }

    // ---- Write output: zeros except out[n,c,start(c)+j] = T[asg[c]][j] ----
    float* orow = out + (size_t)n * (CC * FF);
    #pragma unroll
    for (int k = 0; k < 3; k++) {
        if (k == 2 && lane >= 16) break;
        int p = lane + 32 * k;        // float4 index within row
        int e = 4 * p;                // element index
        int c = e >> 6;               // channel (constant within the float4)
        int aa = asg[0];
        #pragma unroll
        for (int r2 = 1; r2 < 5; r2++) aa = (c == r2) ? asg[r2] : aa;
        int base = (e & 63) - seg_start(c);
        const float* tok = &Ts[aa * DD];
        float4 v;
        v.x = (base     >= 0 && base     < DD) ? tok[base]     : 0.f;
        v.y = (base + 1 >= 0 && base + 1 < DD) ? tok[base + 1] : 0.f;
        v.z = (base + 2 >= 0 && base + 2 < DD) ? tok[base + 2] : 0.f;
        v.w = (base + 3 >= 0 && base + 3 < DD) ? tok[base + 3] : 0.f;
        ((float4*)orow)[p] = v;
    }
}

extern "C" void kernel_launch(void* const* d_in, const int* in_sizes, int n_in,
                              void* d_out, int out_size) {
    const float* pic = (const float*)d_in[0];
    const float* t0  = (const float*)d_in[1];
    const float* t1  = (const float*)d_in[2];
    const float* t2  = (const float*)d_in[3];
    const float* t3  = (const float*)d_in[4];
    const float* t4  = (const float*)d_in[5];
    float* out = (float*)d_out;

    token_kernel<<<NN, 32>>>(pic, t0, t1, t2, t3, t4, out);
}

// round 5
// speedup vs baseline: 1.3600x; 1.0400x over previous
#include <cuda_runtime.h>
#include <cuda_bf16.h>

#define NN 375
#define CC 5
#define FF 64
#define DD 13
#define WPB 4
#define INF30 1e30f

__device__ __forceinline__ int seg_start(int s) { return s == 0 ? 0 : 13 * s - 1; }

__device__ __forceinline__ float tok_load(int q,
                                          const float* __restrict__ t0,
                                          const float* __restrict__ t1,
                                          const float* __restrict__ t2,
                                          const float* __restrict__ t3,
                                          const float* __restrict__ t4) {
    int s = q / DD;
    int j = q - DD * s;
    const float* tp = (s == 0) ? t0 : (s == 1) ? t1 : (s == 2) ? t2 : (s == 3) ? t3 : t4;
    return tp[j];
}

// Monotone map fp32 -> u32 (total order matching <, modulo -0/+0)
__device__ __forceinline__ unsigned f2key(float f) {
    unsigned u = __float_as_uint(f);
    return (u & 0x80000000u) ? ~u : (u | 0x80000000u);
}

__global__ void __launch_bounds__(32 * WPB, 1)
token_kernel(const float* __restrict__ pic,
             const float* __restrict__ t0, const float* __restrict__ t1,
             const float* __restrict__ t2, const float* __restrict__ t3,
             const float* __restrict__ t4,
             float* __restrict__ out) {
    __shared__ float sp[WPB][CC * FF];
    __shared__ float Ts[WPB][CC * DD + 3];

    const int warp = threadIdx.x >> 5;
    const int lane = threadIdx.x & 31;
    const int n = blockIdx.x * WPB + warp;
    if (n >= NN) return;   // whole-warp exit; no block-level sync anywhere

    // ---- Issue ALL global loads up front ----
    const float4* p4 = (const float4*)(pic + (size_t)n * (CC * FF));
    float4 r0 = p4[lane];
    float4 r1 = p4[lane + 32];
    float4 r2 = make_float4(0.f, 0.f, 0.f, 0.f);
    if (lane < 16) r2 = p4[lane + 64];

    float tv0 = tok_load(lane, t0, t1, t2, t3, t4);
    float tv1 = tok_load(lane + 32, t0, t1, t2, t3, t4);
    float tv2 = (lane == 0) ? t4[12] : 0.f;

    // ---- Per-lane channel partials ----
    float s0 = r0.x * r0.x + r0.y * r0.y + r0.z * r0.z + r0.w * r0.w;  // ch0 (lanes<16) / ch1
    float s1 = r1.x * r1.x + r1.y * r1.y + r1.z * r1.z + r1.w * r1.w;  // ch2 / ch3
    float s2 = r2.x * r2.x + r2.y * r2.y + r2.z * r2.z + r2.w * r2.w;  // ch4 (lanes<16 only)

    // 4-stage butterfly within 16-lane halves
    #pragma unroll
    for (int off = 8; off >= 1; off >>= 1) {
        s0 += __shfl_xor_sync(0xffffffffu, s0, off);
        s1 += __shfl_xor_sync(0xffffffffu, s1, off);
        s2 += __shfl_xor_sync(0xffffffffu, s2, off);
    }
    // lanes 0-15: s0=ch0, s1=ch2, s2=ch4 ; lanes 16-31: s0=ch1, s1=ch3

    // ---- Stage row + tokens into shared ----
    float4* sp4 = (float4*)sp[warp];
    sp4[lane]      = r0;
    sp4[lane + 32] = r1;
    if (lane < 16) sp4[lane + 64] = r2;
    Ts[warp][lane]      = tv0;
    Ts[warp][lane + 32] = tv1;
    if (lane == 0) Ts[warp][64] = tv2;

    // Pick up this lane's full_sq[c] (c = lane/5 for lanes < 25)
    int c = lane / 5;
    int s = lane - 5 * c;
    int srcA = ((c & 1) ? 16 : 0);
    float t0s = __shfl_sync(0xffffffffu, s0, srcA);
    float t1s = __shfl_sync(0xffffffffu, s1, srcA);
    float t2s = __shfl_sync(0xffffffffu, s2, 0);
    float fsq = (c < 2) ? t0s : ((c < 4) ? t1s : t2s);

    __syncwarp();

    // ---- Dmat entry per lane (lanes 0..24) ----
    float Dl = INF30;
    if (lane < 25) {
        const float* row = &sp[warp][c * FF];
        const float* tok = &Ts[warp][s * DD];
        int st = seg_start(s);
        float sa = 0.f, sb = 0.f, da = 0.f, db = 0.f;
        #pragma unroll
        for (int j = 0; j < DD; j += 2) {
            float v = row[st + j];
            float d = v - tok[j];
            sa += v * v;
            da += d * d;
            if (j + 1 < DD) {
                float v2 = row[st + j + 1];
                float d2 = v2 - tok[j + 1];
                sb += v2 * v2;
                db += d2 * d2;
            }
        }
        Dl = fsq - (sa + sb) + (da + db);
    }

    // ---- Greedy matching via REDUX + ballot (exact jnp.argmin tie-break) ----
    const unsigned key = f2key(Dl);
    unsigned excl = 0xFE000000u;          // lanes >= 25 permanently excluded
    int asg[5];
    #pragma unroll
    for (int it = 0; it < 5; it++) {
        unsigned k = ((excl >> lane) & 1u) ? 0xFFFFFFFFu : key;
        unsigned mn = __reduce_min_sync(0xffffffffu, k);
        unsigned ball = __ballot_sync(0xffffffffu, k == mn);
        int idx = __ffs(ball) - 1;        // smallest flat index among ties
        int r  = idx / 5;
        int cc = idx - 5 * r;
        excl |= (0x1Fu << (5 * r)) | (0x108421u << cc);
        #pragma unroll
        for (int r2 = 0; r2 < 5; r2++)
            if (r == r2) asg[r2] = cc;
    }

    // ---- Write output ----
    float* orow = out + (size_t)n * (CC * FF);
    #pragma unroll
    for (int k2 = 0; k2 < 3; k2++) {
        if (k2 == 2 && lane >= 16) break;
        int p = lane + 32 * k2;
        int e = 4 * p;
        int ch = e >> 6;
        int aa = asg[0];
        #pragma unroll
        for (int r2 = 1; r2 < 5; r2++) aa = (ch == r2) ? asg[r2] : aa;
        int base = (e & 63) - seg_start(ch);
        const float* tok = &Ts[warp][aa * DD];
        float4 v;
        v.x = (base     >= 0 && base     < DD) ? tok[base]     : 0.f;
        v.y = (base + 1 >= 0 && base + 1 < DD) ? tok[base + 1] : 0.f;
        v.z = (base + 2 >= 0 && base + 2 < DD) ? tok[base + 2] : 0.f;
        v.w = (base + 3 >= 0 && base + 3 < DD) ? tok[base + 3] : 0.f;
        ((float4*)orow)[p] = v;
    }
}

extern "C" void kernel_launch(void* const* d_in, const int* in_sizes, int n_in,
                              void* d_out, int out_size) {
    const float* pic = (const float*)d_in[0];
    const float* t0  = (const float*)d_in[1];
    const float* t1  = (const float*)d_in[2];
    const float* t2  = (const float*)d_in[3];
    const float* t3  = (const float*)d_in[4];
    const float* t4  = (const float*)d_in[5];
    float* out = (float*)d_out;

    const int blocks = (NN + WPB - 1) / WPB;  // 94
    token_kernel<<<blocks, 32 * WPB>>>(pic, t0, t1, t2, t3, t4, out);
}